// round 14
// baseline (speedup 1.0000x reference)
#include <cuda_runtime.h>
#include <cuda_fp16.h>
#include <cstdint>

#define T_TOK 8192
#define H_DIM 2048
#define I_DIM 4096
#define E_NUM 8
#define SWIGLU_ALPHA 1.702f
#define SWIGLU_LIMIT 7.0f

// fp16-staged operands + fp16 activated intermediate
__device__ __half g_xh[(size_t)T_TOK * H_DIM];
__device__ __half g_acth[(size_t)T_TOK * I_DIM];
__device__ __half g_wgh[(size_t)E_NUM * H_DIM * I_DIM];
__device__ __half g_wuh[(size_t)E_NUM * H_DIM * I_DIM];
__device__ __half g_wdh[(size_t)E_NUM * I_DIM * H_DIM];

// ---------------------------------------------------------------------------
// Helpers
// ---------------------------------------------------------------------------
__device__ __forceinline__ uint32_t smem_u32(const void* p) {
    uint32_t a;
    asm("{ .reg .u64 t; cvta.to.shared.u64 t, %1; cvt.u32.u64 %0, t; }" : "=r"(a) : "l"(p));
    return a;
}
__device__ __forceinline__ uint32_t h2_as_u32(__half2 h) {
    return *reinterpret_cast<uint32_t*>(&h);
}
__device__ __forceinline__ void mma16(float c[4],
                                      uint32_t a0, uint32_t a1, uint32_t a2, uint32_t a3,
                                      uint32_t b0, uint32_t b1) {
    asm("mma.sync.aligned.m16n8k16.row.col.f32.f16.f16.f32 "
        "{%0,%1,%2,%3}, {%4,%5,%6,%7}, {%8,%9}, {%0,%1,%2,%3};"
        : "+f"(c[0]), "+f"(c[1]), "+f"(c[2]), "+f"(c[3])
        : "r"(a0), "r"(a1), "r"(a2), "r"(a3), "r"(b0), "r"(b1));
}
#define LDMX4(r0, r1, r2, r3, addr) \
    asm volatile("ldmatrix.sync.aligned.m8n8.x4.shared.b16 {%0,%1,%2,%3}, [%4];" \
        : "=r"(r0), "=r"(r1), "=r"(r2), "=r"(r3) : "r"(addr))
#define LDMX4T(r0, r1, r2, r3, addr) \
    asm volatile("ldmatrix.sync.aligned.m8n8.x4.trans.shared.b16 {%0,%1,%2,%3}, [%4];" \
        : "=r"(r0), "=r"(r1), "=r"(r2), "=r"(r3) : "r"(addr))
#define CP16(dst, src) \
    asm volatile("cp.async.cg.shared.global [%0], [%1], 16;" :: "r"(dst), "l"(src))
#define CP_COMMIT() asm volatile("cp.async.commit_group;")
#define CP_WAIT2()  asm volatile("cp.async.wait_group 2;")

__device__ __forceinline__ float swiglu(float g, float u) {
    g = fminf(g, SWIGLU_LIMIT);
    u = fminf(fmaxf(u, -SWIGLU_LIMIT), SWIGLU_LIMIT);
    float sig = 1.0f / (1.0f + __expf(-SWIGLU_ALPHA * g));
    return (u + 1.0f) * g * sig;
}

// BK = 64 halves per k-tile
constexpr int APADH = 72;                     // 144B row stride -> conflict-free ldmatrix
constexpr int ABYTES12 = 128 * APADH * 2;     // 18432
constexpr int ABYTES3  = 64 * APADH * 2;      // 9216

// ===========================================================================
// Staging: fp32 -> fp16 (RN) for x, gate_w, up_w, down_w in ONE kernel
// ===========================================================================
constexpr int N8_X = T_TOK * H_DIM / 8;                // 2Mi chunks
constexpr int N8_W = E_NUM * H_DIM * I_DIM / 8;        // 8Mi chunks each

__global__ __launch_bounds__(256)
void stage_all_kernel(const float4* __restrict__ x,
                      const float4* __restrict__ gw,
                      const float4* __restrict__ uw,
                      const float4* __restrict__ dw,
                      uint4* __restrict__ xh, uint4* __restrict__ gwh,
                      uint4* __restrict__ uwh, uint4* __restrict__ dwh) {
    int i = blockIdx.x * 256 + threadIdx.x;
    const float4* src;
    uint4* dst;
    int idx;
    if (i < N8_X)                { src = x;  dst = xh;  idx = i; }
    else if (i < N8_X + N8_W)    { src = gw; dst = gwh; idx = i - N8_X; }
    else if (i < N8_X + 2*N8_W)  { src = uw; dst = uwh; idx = i - N8_X - N8_W; }
    else if (i < N8_X + 3*N8_W)  { src = dw; dst = dwh; idx = i - N8_X - 2*N8_W; }
    else return;
    float4 v0 = src[2 * idx], v1 = src[2 * idx + 1];
    uint4 o;
    o.x = h2_as_u32(__floats2half2_rn(v0.x, v0.y));
    o.y = h2_as_u32(__floats2half2_rn(v0.z, v0.w));
    o.z = h2_as_u32(__floats2half2_rn(v1.x, v1.y));
    o.w = h2_as_u32(__floats2half2_rn(v1.z, v1.w));
    dst[idx] = o;
}

// ===========================================================================
// Fused gate+up GEMM + bias + swiglu -> g_acth (fp16)
// CTA 128x128 (both g,u), 256 thr, 8 warps 2x4, warp 64x32/matrix, BK=64
// ===========================================================================
constexpr int BPADH12 = 136;
constexpr int BBYTES12 = 64 * BPADH12 * 2;         // 17408
constexpr int STG12 = 4;
constexpr int STAGE12 = ABYTES12 + 2 * BBYTES12;   // 53248
constexpr int DYN12 = STG12 * STAGE12;             // 212992

__global__ __launch_bounds__(256, 1)
void gemm12(const __half* __restrict__ x,
            const __half* __restrict__ gw,
            const __half* __restrict__ uw,
            const float* __restrict__ gb,
            const float* __restrict__ ub,
            const int* __restrict__ offs,
            __half* __restrict__ act)
{
    extern __shared__ __align__(16) char smraw[];
    const uint32_t sbase = smem_u32(smraw);
    const int tid = threadIdx.x, lane = tid & 31, warp = tid >> 5;
    const int wm = warp >> 2, wn = warp & 3;
    const int gid = lane >> 2, tig = lane & 3;
    const int n0 = blockIdx.x * 128, m0 = blockIdx.y * 128;

    int e = 0;
#pragma unroll
    for (int i = 0; i < E_NUM - 1; i++)
        if (m0 >= offs[i]) e = i + 1;

    const __half* xa  = x + (size_t)m0 * H_DIM;
    const __half* gwa = gw + (size_t)e * H_DIM * I_DIM + n0;
    const __half* uwa = uw + (size_t)e * H_DIM * I_DIM + n0;

    auto issue = [&](int it, int s) {
        const uint32_t sa = sbase + s * STAGE12;
        const int k0 = it * 64;
#pragma unroll
        for (int j = 0; j < 4; j++) {               // A: 128r x 8 chunks = 1024
            int idx = tid + 256 * j;
            int r = idx >> 3, c8 = idx & 7;
            CP16(sa + (uint32_t)(r * APADH + c8 * 8) * 2,
                 xa + (size_t)r * H_DIM + k0 + c8 * 8);
        }
        const uint32_t sg = sa + ABYTES12, su = sg + BBYTES12;
#pragma unroll
        for (int j = 0; j < 4; j++) {               // each B: 64r x 16 chunks = 1024
            int idx = tid + 256 * j;
            int r = idx >> 4, c8 = idx & 15;
            uint32_t off = (uint32_t)(r * BPADH12 + c8 * 8) * 2;
            CP16(sg + off, gwa + (size_t)(k0 + r) * I_DIM + c8 * 8);
            CP16(su + off, uwa + (size_t)(k0 + r) * I_DIM + c8 * 8);
        }
        CP_COMMIT();
    };

    float cg[4][4][4] = {}, cu[4][4][4] = {};

    issue(0, 0); issue(1, 1); issue(2, 2);

    const uint32_t aRow = wm * 64 + (lane & 15);
    const uint32_t aCol = (lane >> 4) * 8;
    const uint32_t bRow = (lane & 15);
    const uint32_t bCol = wn * 32 + (lane >> 4) * 8;

    const int NIT = H_DIM / 64;   // 32
#pragma unroll 1
    for (int it0 = 0; it0 < NIT; it0 += 4) {
#pragma unroll
        for (int sub = 0; sub < 4; ++sub) {
            const int it = it0 + sub;
            CP_WAIT2();
            __syncthreads();

            const uint32_t sA = sbase + sub * STAGE12;
            const uint32_t sG = sA + ABYTES12;
            const uint32_t sU = sG + BBYTES12;

#pragma unroll
            for (int ks = 0; ks < 4; ++ks) {
                uint32_t a[4][4];
#pragma unroll
                for (int mf = 0; mf < 4; mf++) {
                    uint32_t ad = sA + ((aRow + mf * 16) * APADH + aCol + ks * 16) * 2;
                    LDMX4(a[mf][0], a[mf][1], a[mf][2], a[mf][3], ad);
                }
#pragma unroll
                for (int nfp = 0; nfp < 2; nfp++) {
                    uint32_t boff = ((bRow + ks * 16) * BPADH12 + bCol + nfp * 16) * 2;
                    uint32_t bg0, bg1, bg2, bg3, bu0, bu1, bu2, bu3;
                    LDMX4T(bg0, bg1, bg2, bg3, sG + boff);
                    LDMX4T(bu0, bu1, bu2, bu3, sU + boff);
#pragma unroll
                    for (int mf = 0; mf < 4; mf++) {
                        mma16(cg[mf][2 * nfp],     a[mf][0], a[mf][1], a[mf][2], a[mf][3], bg0, bg1);
                        mma16(cg[mf][2 * nfp + 1], a[mf][0], a[mf][1], a[mf][2], a[mf][3], bg2, bg3);
                        mma16(cu[mf][2 * nfp],     a[mf][0], a[mf][1], a[mf][2], a[mf][3], bu0, bu1);
                        mma16(cu[mf][2 * nfp + 1], a[mf][0], a[mf][1], a[mf][2], a[mf][3], bu2, bu3);
                    }
                }
            }
            if (it + 3 < NIT) issue(it + 3, (it + 3) & 3);
            else CP_COMMIT();
        }
    }

    // Epilogue: bias + swiglu -> fp16 act
#pragma unroll
    for (int nf = 0; nf < 4; nf++) {
        const int c0 = n0 + wn * 32 + nf * 8 + 2 * tig;
        const float2 gbv = *reinterpret_cast<const float2*>(gb + (size_t)e * I_DIM + c0);
        const float2 ubv = *reinterpret_cast<const float2*>(ub + (size_t)e * I_DIM + c0);
#pragma unroll
        for (int mf = 0; mf < 4; mf++) {
            const int r0 = m0 + wm * 64 + mf * 16 + gid;
            float o00 = swiglu(cg[mf][nf][0] + gbv.x, cu[mf][nf][0] + ubv.x);
            float o01 = swiglu(cg[mf][nf][1] + gbv.y, cu[mf][nf][1] + ubv.y);
            float o10 = swiglu(cg[mf][nf][2] + gbv.x, cu[mf][nf][2] + ubv.x);
            float o11 = swiglu(cg[mf][nf][3] + gbv.y, cu[mf][nf][3] + ubv.y);
            *reinterpret_cast<__half2*>(act + (size_t)r0 * I_DIM + c0) = __floats2half2_rn(o00, o01);
            *reinterpret_cast<__half2*>(act + (size_t)(r0 + 8) * I_DIM + c0) = __floats2half2_rn(o10, o11);
        }
    }
}

// ===========================================================================
// Down GEMM + bias -> out (fp32).
// CTA 64x256, 256 thr, 8 warps 2x4, warp 32x64, BK=64
// Grid = 8 x 128 = 1024 CTAs -> ~7 full waves (kills tail quantization)
// ===========================================================================
constexpr int BPADH3 = 264;
constexpr int BBYTES3 = 64 * BPADH3 * 2;        // 33792
constexpr int STG3 = 4;
constexpr int STAGE3 = ABYTES3 + BBYTES3;       // 43008
constexpr int DYN3 = STG3 * STAGE3;             // 172032

__global__ __launch_bounds__(256, 1)
void gemm3(const __half* __restrict__ act,
           const __half* __restrict__ dw,
           const float* __restrict__ db,
           const int* __restrict__ offs,
           float* __restrict__ out)
{
    extern __shared__ __align__(16) char smraw[];
    const uint32_t sbase = smem_u32(smraw);
    const int tid = threadIdx.x, lane = tid & 31, warp = tid >> 5;
    const int wm = warp >> 2, wn = warp & 3;
    const int gid = lane >> 2, tig = lane & 3;
    const int n0 = blockIdx.x * 256, m0 = blockIdx.y * 64;

    int e = 0;
#pragma unroll
    for (int i = 0; i < E_NUM - 1; i++)
        if (m0 >= offs[i]) e = i + 1;

    const __half* aa  = act + (size_t)m0 * I_DIM;
    const __half* dwa = dw + (size_t)e * I_DIM * H_DIM + n0;

    auto issue = [&](int it, int s) {
        const uint32_t sa = sbase + s * STAGE3;
        const int k0 = it * 64;
#pragma unroll
        for (int j = 0; j < 2; j++) {               // A: 64r x 8 chunks = 512
            int idx = tid + 256 * j;
            int r = idx >> 3, c8 = idx & 7;
            CP16(sa + (uint32_t)(r * APADH + c8 * 8) * 2,
                 aa + (size_t)r * I_DIM + k0 + c8 * 8);
        }
        const uint32_t sb = sa + ABYTES3;
#pragma unroll
        for (int j = 0; j < 8; j++) {               // B: 64r x 32 chunks = 2048
            int idx = tid + 256 * j;
            int r = idx >> 5, c8 = idx & 31;
            CP16(sb + (uint32_t)(r * BPADH3 + c8 * 8) * 2,
                 dwa + (size_t)(k0 + r) * H_DIM + c8 * 8);
        }
        CP_COMMIT();
    };

    float cc[2][8][4] = {};

    issue(0, 0); issue(1, 1); issue(2, 2);

    const uint32_t aRow = wm * 32 + (lane & 15);
    const uint32_t aCol = (lane >> 4) * 8;
    const uint32_t bRow = (lane & 15);
    const uint32_t bCol = wn * 64 + (lane >> 4) * 8;

    const int NIT = I_DIM / 64;   // 64
#pragma unroll 1
    for (int it0 = 0; it0 < NIT; it0 += 4) {
#pragma unroll
        for (int sub = 0; sub < 4; ++sub) {
            const int it = it0 + sub;
            CP_WAIT2();
            __syncthreads();

            const uint32_t sA = sbase + sub * STAGE3;
            const uint32_t sB = sA + ABYTES3;

#pragma unroll
            for (int ks = 0; ks < 4; ++ks) {
                uint32_t a[2][4];
#pragma unroll
                for (int mf = 0; mf < 2; mf++) {
                    uint32_t ad = sA + ((aRow + mf * 16) * APADH + aCol + ks * 16) * 2;
                    LDMX4(a[mf][0], a[mf][1], a[mf][2], a[mf][3], ad);
                }
#pragma unroll
                for (int nfp = 0; nfp < 4; nfp++) {
                    uint32_t b0, b1, b2, b3;
                    LDMX4T(b0, b1, b2, b3,
                           sB + ((bRow + ks * 16) * BPADH3 + bCol + nfp * 16) * 2);
#pragma unroll
                    for (int mf = 0; mf < 2; mf++) {
                        mma16(cc[mf][2 * nfp],     a[mf][0], a[mf][1], a[mf][2], a[mf][3], b0, b1);
                        mma16(cc[mf][2 * nfp + 1], a[mf][0], a[mf][1], a[mf][2], a[mf][3], b2, b3);
                    }
                }
            }
            if (it + 3 < NIT) issue(it + 3, (it + 3) & 3);
            else CP_COMMIT();
        }
    }

    // Epilogue: + down_b -> out
#pragma unroll
    for (int nf = 0; nf < 8; nf++) {
        const int c0 = n0 + wn * 64 + nf * 8 + 2 * tig;
        const float2 bv = *reinterpret_cast<const float2*>(db + (size_t)e * H_DIM + c0);
#pragma unroll
        for (int mf = 0; mf < 2; mf++) {
            const int r0 = m0 + wm * 32 + mf * 16 + gid;
            float2 o0, o1;
            o0.x = cc[mf][nf][0] + bv.x;
            o0.y = cc[mf][nf][1] + bv.y;
            o1.x = cc[mf][nf][2] + bv.x;
            o1.y = cc[mf][nf][3] + bv.y;
            *reinterpret_cast<float2*>(out + (size_t)r0 * H_DIM + c0) = o0;
            *reinterpret_cast<float2*>(out + (size_t)(r0 + 8) * H_DIM + c0) = o1;
        }
    }
}

// ===========================================================================
// Launch
// ===========================================================================
extern "C" void kernel_launch(void* const* d_in, const int* in_sizes, int n_in,
                              void* d_out, int out_size)
{
    const float* x      = (const float*)d_in[0];
    const int*   offs   = (const int*)d_in[1];
    const float* gate_w = (const float*)d_in[2];
    const float* up_w   = (const float*)d_in[3];
    const float* down_w = (const float*)d_in[4];
    const float* gate_b = (const float*)d_in[5];
    const float* up_b   = (const float*)d_in[6];
    const float* down_b = (const float*)d_in[7];
    float* out = (float*)d_out;

    __half *pxh, *pacth, *pwgh, *pwuh, *pwdh;
    cudaGetSymbolAddress((void**)&pxh,   g_xh);
    cudaGetSymbolAddress((void**)&pacth, g_acth);
    cudaGetSymbolAddress((void**)&pwgh,  g_wgh);
    cudaGetSymbolAddress((void**)&pwuh,  g_wuh);
    cudaGetSymbolAddress((void**)&pwdh,  g_wdh);

    cudaFuncSetAttribute(gemm12, cudaFuncAttributeMaxDynamicSharedMemorySize, DYN12);
    cudaFuncSetAttribute(gemm3,  cudaFuncAttributeMaxDynamicSharedMemorySize, DYN3);

    // Staging: single kernel converts x + all three weight tensors
    {
        int total = N8_X + 3 * N8_W;
        stage_all_kernel<<<(total + 255) / 256, 256>>>(
            (const float4*)x, (const float4*)gate_w, (const float4*)up_w,
            (const float4*)down_w,
            (uint4*)pxh, (uint4*)pwgh, (uint4*)pwuh, (uint4*)pwdh);
    }
    {
        dim3 grid(I_DIM / 128, T_TOK / 128);   // 32 x 64 = 2048 CTAs
        gemm12<<<grid, 256, DYN12>>>(pxh, pwgh, pwuh, gate_b, up_b, offs, pacth);
    }
    {
        dim3 grid(H_DIM / 256, T_TOK / 64);    // 8 x 128 = 1024 CTAs
        gemm3<<<grid, 256, DYN3>>>(pacth, pwdh, down_b, offs, out);
    }
}

// round 17
// speedup vs baseline: 1.0313x; 1.0313x over previous
#include <cuda_runtime.h>
#include <cuda_fp16.h>
#include <cstdint>

#define T_TOK 8192
#define H_DIM 2048
#define I_DIM 4096
#define E_NUM 8
#define SWIGLU_ALPHA 1.702f
#define SWIGLU_LIMIT 7.0f

// fp16-staged operands + fp16 activated intermediate
__device__ __half g_xh[(size_t)T_TOK * H_DIM];
__device__ __half g_acth[(size_t)T_TOK * I_DIM];
__device__ __half g_wgh[(size_t)E_NUM * H_DIM * I_DIM];
__device__ __half g_wuh[(size_t)E_NUM * H_DIM * I_DIM];
__device__ __half g_wdh[(size_t)E_NUM * I_DIM * H_DIM];

// ---------------------------------------------------------------------------
// Helpers
// ---------------------------------------------------------------------------
__device__ __forceinline__ uint32_t smem_u32(const void* p) {
    uint32_t a;
    asm("{ .reg .u64 t; cvta.to.shared.u64 t, %1; cvt.u32.u64 %0, t; }" : "=r"(a) : "l"(p));
    return a;
}
__device__ __forceinline__ uint32_t h2_as_u32(__half2 h) {
    return *reinterpret_cast<uint32_t*>(&h);
}
__device__ __forceinline__ void mma16(float c[4],
                                      uint32_t a0, uint32_t a1, uint32_t a2, uint32_t a3,
                                      uint32_t b0, uint32_t b1) {
    asm("mma.sync.aligned.m16n8k16.row.col.f32.f16.f16.f32 "
        "{%0,%1,%2,%3}, {%4,%5,%6,%7}, {%8,%9}, {%0,%1,%2,%3};"
        : "+f"(c[0]), "+f"(c[1]), "+f"(c[2]), "+f"(c[3])
        : "r"(a0), "r"(a1), "r"(a2), "r"(a3), "r"(b0), "r"(b1));
}
#define LDMX4(r0, r1, r2, r3, addr) \
    asm volatile("ldmatrix.sync.aligned.m8n8.x4.shared.b16 {%0,%1,%2,%3}, [%4];" \
        : "=r"(r0), "=r"(r1), "=r"(r2), "=r"(r3) : "r"(addr))
#define LDMX4T(r0, r1, r2, r3, addr) \
    asm volatile("ldmatrix.sync.aligned.m8n8.x4.trans.shared.b16 {%0,%1,%2,%3}, [%4];" \
        : "=r"(r0), "=r"(r1), "=r"(r2), "=r"(r3) : "r"(addr))
#define CP16(dst, src) \
    asm volatile("cp.async.cg.shared.global [%0], [%1], 16;" :: "r"(dst), "l"(src))
#define CP_COMMIT() asm volatile("cp.async.commit_group;")
#define CP_WAIT2()  asm volatile("cp.async.wait_group 2;")

__device__ __forceinline__ float swiglu(float g, float u) {
    g = fminf(g, SWIGLU_LIMIT);
    u = fminf(fmaxf(u, -SWIGLU_LIMIT), SWIGLU_LIMIT);
    float sig = 1.0f / (1.0f + __expf(-SWIGLU_ALPHA * g));
    return (u + 1.0f) * g * sig;
}

// BK = 64 halves per k-tile
constexpr int APADH = 72;                     // 144B row stride -> conflict-free ldmatrix
constexpr int ABYTES = 128 * APADH * 2;       // 18432

constexpr int N8_X  = T_TOK * H_DIM / 8;               // 2Mi chunks
constexpr int N8_W  = E_NUM * H_DIM * I_DIM / 8;       // 8Mi chunks each
constexpr int N8_DW = E_NUM * I_DIM * H_DIM / 8;       // 8Mi chunks

// ===========================================================================
// Staging: fp32 -> fp16 (RN) for x, gate_w, up_w (down_w handled inside gemm12)
// ===========================================================================
__global__ __launch_bounds__(256)
void stage_xgu_kernel(const float4* __restrict__ x,
                      const float4* __restrict__ gw,
                      const float4* __restrict__ uw,
                      uint4* __restrict__ xh, uint4* __restrict__ gwh,
                      uint4* __restrict__ uwh) {
    int i = blockIdx.x * 256 + threadIdx.x;
    const float4* src;
    uint4* dst;
    int idx;
    if (i < N8_X)               { src = x;  dst = xh;  idx = i; }
    else if (i < N8_X + N8_W)   { src = gw; dst = gwh; idx = i - N8_X; }
    else if (i < N8_X + 2*N8_W) { src = uw; dst = uwh; idx = i - N8_X - N8_W; }
    else return;
    float4 v0 = src[2 * idx], v1 = src[2 * idx + 1];
    uint4 o;
    o.x = h2_as_u32(__floats2half2_rn(v0.x, v0.y));
    o.y = h2_as_u32(__floats2half2_rn(v0.z, v0.w));
    o.z = h2_as_u32(__floats2half2_rn(v1.x, v1.y));
    o.w = h2_as_u32(__floats2half2_rn(v1.z, v1.w));
    dst[idx] = o;
}

// ===========================================================================
// Fused gate+up GEMM + bias + swiglu -> g_acth (fp16)
// CTA 128x128 (both g,u), 256 thr, 8 warps 2x4, warp 64x32/matrix, BK=64
// Also converts a 1/2048 slice of down_w fp32->fp16 at CTA end (overlapped
// staging for gemm3; early-wave CTAs' conversions hide under later compute).
// ===========================================================================
constexpr int BPADH12 = 136;
constexpr int BBYTES12 = 64 * BPADH12 * 2;         // 17408
constexpr int STG12 = 4;
constexpr int STAGE12 = ABYTES + 2 * BBYTES12;     // 53248
constexpr int DYN12 = STG12 * STAGE12;             // 212992

__global__ __launch_bounds__(256, 1)
void gemm12(const __half* __restrict__ x,
            const __half* __restrict__ gw,
            const __half* __restrict__ uw,
            const float* __restrict__ gb,
            const float* __restrict__ ub,
            const int* __restrict__ offs,
            __half* __restrict__ act,
            const float4* __restrict__ dwf,
            uint4* __restrict__ dwh)
{
    extern __shared__ __align__(16) char smraw[];
    const uint32_t sbase = smem_u32(smraw);
    const int tid = threadIdx.x, lane = tid & 31, warp = tid >> 5;
    const int wm = warp >> 2, wn = warp & 3;
    const int gid = lane >> 2, tig = lane & 3;
    const int n0 = blockIdx.x * 128, m0 = blockIdx.y * 128;

    int e = 0;
#pragma unroll
    for (int i = 0; i < E_NUM - 1; i++)
        if (m0 >= offs[i]) e = i + 1;

    const __half* xa  = x + (size_t)m0 * H_DIM;
    const __half* gwa = gw + (size_t)e * H_DIM * I_DIM + n0;
    const __half* uwa = uw + (size_t)e * H_DIM * I_DIM + n0;

    auto issue = [&](int it, int s) {
        const uint32_t sa = sbase + s * STAGE12;
        const int k0 = it * 64;
#pragma unroll
        for (int j = 0; j < 4; j++) {               // A: 128r x 8 chunks = 1024
            int idx = tid + 256 * j;
            int r = idx >> 3, c8 = idx & 7;
            CP16(sa + (uint32_t)(r * APADH + c8 * 8) * 2,
                 xa + (size_t)r * H_DIM + k0 + c8 * 8);
        }
        const uint32_t sg = sa + ABYTES, su = sg + BBYTES12;
#pragma unroll
        for (int j = 0; j < 4; j++) {               // each B: 64r x 16 chunks = 1024
            int idx = tid + 256 * j;
            int r = idx >> 4, c8 = idx & 15;
            uint32_t off = (uint32_t)(r * BPADH12 + c8 * 8) * 2;
            CP16(sg + off, gwa + (size_t)(k0 + r) * I_DIM + c8 * 8);
            CP16(su + off, uwa + (size_t)(k0 + r) * I_DIM + c8 * 8);
        }
        CP_COMMIT();
    };

    float cg[4][4][4] = {}, cu[4][4][4] = {};

    issue(0, 0); issue(1, 1); issue(2, 2);

    const uint32_t aRow = wm * 64 + (lane & 15);
    const uint32_t aCol = (lane >> 4) * 8;
    const uint32_t bRow = (lane & 15);
    const uint32_t bCol = wn * 32 + (lane >> 4) * 8;

    const int NIT = H_DIM / 64;   // 32
#pragma unroll 1
    for (int it0 = 0; it0 < NIT; it0 += 4) {
#pragma unroll
        for (int sub = 0; sub < 4; ++sub) {
            const int it = it0 + sub;
            CP_WAIT2();
            __syncthreads();

            const uint32_t sA = sbase + sub * STAGE12;
            const uint32_t sG = sA + ABYTES;
            const uint32_t sU = sG + BBYTES12;

#pragma unroll
            for (int ks = 0; ks < 4; ++ks) {
                uint32_t a[4][4];
#pragma unroll
                for (int mf = 0; mf < 4; mf++) {
                    uint32_t ad = sA + ((aRow + mf * 16) * APADH + aCol + ks * 16) * 2;
                    LDMX4(a[mf][0], a[mf][1], a[mf][2], a[mf][3], ad);
                }
#pragma unroll
                for (int nfp = 0; nfp < 2; nfp++) {
                    uint32_t boff = ((bRow + ks * 16) * BPADH12 + bCol + nfp * 16) * 2;
                    uint32_t bg0, bg1, bg2, bg3, bu0, bu1, bu2, bu3;
                    LDMX4T(bg0, bg1, bg2, bg3, sG + boff);
                    LDMX4T(bu0, bu1, bu2, bu3, sU + boff);
#pragma unroll
                    for (int mf = 0; mf < 4; mf++) {
                        mma16(cg[mf][2 * nfp],     a[mf][0], a[mf][1], a[mf][2], a[mf][3], bg0, bg1);
                        mma16(cg[mf][2 * nfp + 1], a[mf][0], a[mf][1], a[mf][2], a[mf][3], bg2, bg3);
                        mma16(cu[mf][2 * nfp],     a[mf][0], a[mf][1], a[mf][2], a[mf][3], bu0, bu1);
                        mma16(cu[mf][2 * nfp + 1], a[mf][0], a[mf][1], a[mf][2], a[mf][3], bu2, bu3);
                    }
                }
            }
            if (it + 3 < NIT) issue(it + 3, (it + 3) & 3);
            else CP_COMMIT();
        }
    }

    // Epilogue: bias + swiglu -> fp16 act
#pragma unroll
    for (int nf = 0; nf < 4; nf++) {
        const int c0 = n0 + wn * 32 + nf * 8 + 2 * tig;
        const float2 gbv = *reinterpret_cast<const float2*>(gb + (size_t)e * I_DIM + c0);
        const float2 ubv = *reinterpret_cast<const float2*>(ub + (size_t)e * I_DIM + c0);
#pragma unroll
        for (int mf = 0; mf < 4; mf++) {
            const int r0 = m0 + wm * 64 + mf * 16 + gid;
            float o00 = swiglu(cg[mf][nf][0] + gbv.x, cu[mf][nf][0] + ubv.x);
            float o01 = swiglu(cg[mf][nf][1] + gbv.y, cu[mf][nf][1] + ubv.y);
            float o10 = swiglu(cg[mf][nf][2] + gbv.x, cu[mf][nf][2] + ubv.x);
            float o11 = swiglu(cg[mf][nf][3] + gbv.y, cu[mf][nf][3] + ubv.y);
            *reinterpret_cast<__half2*>(act + (size_t)r0 * I_DIM + c0) = __floats2half2_rn(o00, o01);
            *reinterpret_cast<__half2*>(act + (size_t)(r0 + 8) * I_DIM + c0) = __floats2half2_rn(o10, o11);
        }
    }

    // Overlapped staging: convert this CTA's 1/2048 slice of down_w to fp16
    {
        const int cta = blockIdx.y * gridDim.x + blockIdx.x;     // 0..2047
        const int per_cta = N8_DW / 2048;                        // 4096 chunks
        const float4* src = dwf + (size_t)cta * per_cta * 2;
        uint4* dst = dwh + (size_t)cta * per_cta;
#pragma unroll 4
        for (int j = tid; j < per_cta; j += 256) {
            float4 v0 = src[2 * j], v1 = src[2 * j + 1];
            uint4 o;
            o.x = h2_as_u32(__floats2half2_rn(v0.x, v0.y));
            o.y = h2_as_u32(__floats2half2_rn(v0.z, v0.w));
            o.z = h2_as_u32(__floats2half2_rn(v1.x, v1.y));
            o.w = h2_as_u32(__floats2half2_rn(v1.z, v1.w));
            dst[j] = o;
        }
    }
}

// ===========================================================================
// Down GEMM + bias -> out (fp32). CTA 128x256, 8 warps 2x4, warp 64x64, BK=64
// ===========================================================================
constexpr int BPADH3 = 264;
constexpr int BBYTES3 = 64 * BPADH3 * 2;        // 33792
constexpr int STG3 = 4;
constexpr int STAGE3 = ABYTES + BBYTES3;        // 52224
constexpr int DYN3 = STG3 * STAGE3;             // 208896

__global__ __launch_bounds__(256, 1)
void gemm3(const __half* __restrict__ act,
           const __half* __restrict__ dw,
           const float* __restrict__ db,
           const int* __restrict__ offs,
           float* __restrict__ out)
{
    extern __shared__ __align__(16) char smraw[];
    const uint32_t sbase = smem_u32(smraw);
    const int tid = threadIdx.x, lane = tid & 31, warp = tid >> 5;
    const int wm = warp >> 2, wn = warp & 3;
    const int gid = lane >> 2, tig = lane & 3;
    const int n0 = blockIdx.x * 256, m0 = blockIdx.y * 128;

    int e = 0;
#pragma unroll
    for (int i = 0; i < E_NUM - 1; i++)
        if (m0 >= offs[i]) e = i + 1;

    const __half* aa  = act + (size_t)m0 * I_DIM;
    const __half* dwa = dw + (size_t)e * I_DIM * H_DIM + n0;

    auto issue = [&](int it, int s) {
        const uint32_t sa = sbase + s * STAGE3;
        const int k0 = it * 64;
#pragma unroll
        for (int j = 0; j < 4; j++) {               // A: 1024 chunks
            int idx = tid + 256 * j;
            int r = idx >> 3, c8 = idx & 7;
            CP16(sa + (uint32_t)(r * APADH + c8 * 8) * 2,
                 aa + (size_t)r * I_DIM + k0 + c8 * 8);
        }
        const uint32_t sb = sa + ABYTES;
#pragma unroll
        for (int j = 0; j < 8; j++) {               // B: 64r x 32 chunks = 2048
            int idx = tid + 256 * j;
            int r = idx >> 5, c8 = idx & 31;
            CP16(sb + (uint32_t)(r * BPADH3 + c8 * 8) * 2,
                 dwa + (size_t)(k0 + r) * H_DIM + c8 * 8);
        }
        CP_COMMIT();
    };

    float cc[4][8][4] = {};

    issue(0, 0); issue(1, 1); issue(2, 2);

    const uint32_t aRow = wm * 64 + (lane & 15);
    const uint32_t aCol = (lane >> 4) * 8;
    const uint32_t bRow = (lane & 15);
    const uint32_t bCol = wn * 64 + (lane >> 4) * 8;

    const int NIT = I_DIM / 64;   // 64
#pragma unroll 1
    for (int it0 = 0; it0 < NIT; it0 += 4) {
#pragma unroll
        for (int sub = 0; sub < 4; ++sub) {
            const int it = it0 + sub;
            CP_WAIT2();
            __syncthreads();

            const uint32_t sA = sbase + sub * STAGE3;
            const uint32_t sB = sA + ABYTES;

#pragma unroll
            for (int ks = 0; ks < 4; ++ks) {
                uint32_t a[4][4];
#pragma unroll
                for (int mf = 0; mf < 4; mf++) {
                    uint32_t ad = sA + ((aRow + mf * 16) * APADH + aCol + ks * 16) * 2;
                    LDMX4(a[mf][0], a[mf][1], a[mf][2], a[mf][3], ad);
                }
#pragma unroll
                for (int nfp = 0; nfp < 4; nfp++) {
                    uint32_t b0, b1, b2, b3;
                    LDMX4T(b0, b1, b2, b3,
                           sB + ((bRow + ks * 16) * BPADH3 + bCol + nfp * 16) * 2);
#pragma unroll
                    for (int mf = 0; mf < 4; mf++) {
                        mma16(cc[mf][2 * nfp],     a[mf][0], a[mf][1], a[mf][2], a[mf][3], b0, b1);
                        mma16(cc[mf][2 * nfp + 1], a[mf][0], a[mf][1], a[mf][2], a[mf][3], b2, b3);
                    }
                }
            }
            if (it + 3 < NIT) issue(it + 3, (it + 3) & 3);
            else CP_COMMIT();
        }
    }

    // Epilogue: + down_b -> out
#pragma unroll
    for (int nf = 0; nf < 8; nf++) {
        const int c0 = n0 + wn * 64 + nf * 8 + 2 * tig;
        const float2 bv = *reinterpret_cast<const float2*>(db + (size_t)e * H_DIM + c0);
#pragma unroll
        for (int mf = 0; mf < 4; mf++) {
            const int r0 = m0 + wm * 64 + mf * 16 + gid;
            float2 o0, o1;
            o0.x = cc[mf][nf][0] + bv.x;
            o0.y = cc[mf][nf][1] + bv.y;
            o1.x = cc[mf][nf][2] + bv.x;
            o1.y = cc[mf][nf][3] + bv.y;
            *reinterpret_cast<float2*>(out + (size_t)r0 * H_DIM + c0) = o0;
            *reinterpret_cast<float2*>(out + (size_t)(r0 + 8) * H_DIM + c0) = o1;
        }
    }
}

// ===========================================================================
// Launch
// ===========================================================================
extern "C" void kernel_launch(void* const* d_in, const int* in_sizes, int n_in,
                              void* d_out, int out_size)
{
    const float* x      = (const float*)d_in[0];
    const int*   offs   = (const int*)d_in[1];
    const float* gate_w = (const float*)d_in[2];
    const float* up_w   = (const float*)d_in[3];
    const float* down_w = (const float*)d_in[4];
    const float* gate_b = (const float*)d_in[5];
    const float* up_b   = (const float*)d_in[6];
    const float* down_b = (const float*)d_in[7];
    float* out = (float*)d_out;

    __half *pxh, *pacth, *pwgh, *pwuh, *pwdh;
    cudaGetSymbolAddress((void**)&pxh,   g_xh);
    cudaGetSymbolAddress((void**)&pacth, g_acth);
    cudaGetSymbolAddress((void**)&pwgh,  g_wgh);
    cudaGetSymbolAddress((void**)&pwuh,  g_wuh);
    cudaGetSymbolAddress((void**)&pwdh,  g_wdh);

    cudaFuncSetAttribute(gemm12, cudaFuncAttributeMaxDynamicSharedMemorySize, DYN12);
    cudaFuncSetAttribute(gemm3,  cudaFuncAttributeMaxDynamicSharedMemorySize, DYN3);

    // Staging: x + gate_w + up_w (down_w converted inside gemm12, overlapped)
    {
        int total = N8_X + 2 * N8_W;
        stage_xgu_kernel<<<(total + 255) / 256, 256>>>(
            (const float4*)x, (const float4*)gate_w, (const float4*)up_w,
            (uint4*)pxh, (uint4*)pwgh, (uint4*)pwuh);
    }
    {
        dim3 grid(I_DIM / 128, T_TOK / 128);   // 32 x 64 = 2048 CTAs
        gemm12<<<grid, 256, DYN12>>>(pxh, pwgh, pwuh, gate_b, up_b, offs, pacth,
                                     (const float4*)down_w, (uint4*)pwdh);
    }
    {
        dim3 grid(H_DIM / 256, T_TOK / 128);   // 8 x 64 = 512 CTAs
        gemm3<<<grid, 256, DYN3>>>(pacth, pwdh, down_b, offs, out);
    }
}